// round 11
// baseline (speedup 1.0000x reference)
#include <cuda_runtime.h>
#include <cuda_fp16.h>
#include <cstdint>

// ============================================================================
// INT4Linear on GB300 — persistent tcgen05 GEMM with FUSED, OVERLAPPED prepass.
//   out[M,N] = x[M,K] @ W[N,K]^T + bias     M=8192 N=4096 K=4096
// R10 ncu: gemm 200.5us (tensor 59.3%), prepass ~40us serial. Prepass is
// DRAM-bound (288MB) and unshrinkable -> hide it inside the GEMM: the 8
// epilogue warps (idle for the first ~2 tiles) dequant/convert all blocks
// first, publishing per-block ready flags; the producer acquire-polls flags
// until a global done-counter saturates. GEMM structure = R10 (measured).
// k0: zero flags. k1: fused GEMM.
// ============================================================================

#if defined(__CUDA_ARCH_FEAT_SM103_ALL) || defined(__CUDA_ARCH_FEAT_SM100_ALL)
#define TC_PATH 1
#else
#define TC_PATH 0
#endif

#define KC_ELEMS 64
#define BLK_BYTES 16384
#define STAGES 4
#define STAGE_BYTES (3 * BLK_BYTES)   // A 16KB + B 32KB
#define SMEM_STAGE0 1024
#define SMEM_TOTAL_GEMM (SMEM_STAGE0 + STAGES * STAGE_BYTES)   // 197632
#define THREADS 320

__device__ __half g_W[4096u * 4096u];   // 32 MB, [N/256][K/64][2][128x64] SW128
__device__ __half g_X[8192u * 4096u];   // 64 MB, [M/128][K/64][128x64] SW128
// flags: [0,2048) W blocks, [2048,6144) X blocks, [6144] done counter
__device__ int    g_flags[6145];

__host__ __device__ __forceinline__ uint32_t swz128(uint32_t o) {
    return o ^ ((o >> 3) & 0x70);
}
__device__ __forceinline__ uint32_t smem_u32(const void* p) {
    return (uint32_t)__cvta_generic_to_shared(p);
}
__device__ __forceinline__ int ld_acq(const int* p) {
    int v;
    asm volatile("ld.acquire.gpu.global.b32 %0, [%1];" : "=r"(v) : "l"(p) : "memory");
    return v;
}
__device__ __forceinline__ void st_rel(int* p, int v) {
    asm volatile("st.release.gpu.global.b32 [%0], %1;" :: "l"(p), "r"(v) : "memory");
}
__device__ __forceinline__ void fence_proxy_async_() {
    asm volatile("fence.proxy.async;" ::: "memory");
}

// ---------------------------------------------------------------------------
#if TC_PATH
__device__ __forceinline__ void mbar_init(uint32_t a, uint32_t cnt) {
    asm volatile("mbarrier.init.shared.b64 [%0], %1;" :: "r"(a), "r"(cnt) : "memory");
}
__device__ __forceinline__ void mbar_arrive(uint32_t a) {
    asm volatile("mbarrier.arrive.shared.b64 _, [%0];" :: "r"(a) : "memory");
}
__device__ __forceinline__ void mbar_expect_tx(uint32_t a, uint32_t bytes) {
    asm volatile("mbarrier.arrive.expect_tx.shared.b64 _, [%0], %1;"
                 :: "r"(a), "r"(bytes) : "memory");
}
__device__ __forceinline__ void mbar_wait(uint32_t a, uint32_t parity) {
    uint32_t done;
    asm volatile(
        "{\n\t.reg .pred p;\n\t"
        "mbarrier.try_wait.parity.acquire.cta.shared::cta.b64 p, [%1], %2;\n\t"
        "selp.b32 %0, 1, 0, p;\n\t}"
        : "=r"(done) : "r"(a), "r"(parity) : "memory");
    if (!done) {
        asm volatile(
            "{\n\t.reg .pred P1;\n\t"
            "W0_%=:\n\t"
            "mbarrier.try_wait.parity.acquire.cta.shared::cta.b64 P1, [%0], %1, 0x989680;\n\t"
            "@P1 bra.uni W1_%=;\n\t"
            "bra.uni W0_%=;\n\t"
            "W1_%=:\n\t}"
            :: "r"(a), "r"(parity) : "memory");
    }
}
__device__ __forceinline__ void bulk_g2s(uint32_t dst, const void* src,
                                         uint32_t bytes, uint32_t mbar) {
    asm volatile(
        "cp.async.bulk.shared::cluster.global.mbarrier::complete_tx::bytes "
        "[%0], [%1], %2, [%3];"
        :: "r"(dst), "l"(src), "r"(bytes), "r"(mbar) : "memory");
}
__device__ __forceinline__ void tmem_alloc(uint32_t smem_slot, uint32_t ncols) {
    asm volatile("tcgen05.alloc.cta_group::1.sync.aligned.shared::cta.b32 [%0], %1;"
                 :: "r"(smem_slot), "r"(ncols) : "memory");
}
__device__ __forceinline__ void tmem_relinquish() {
    asm volatile("tcgen05.relinquish_alloc_permit.cta_group::1.sync.aligned;");
}
__device__ __forceinline__ void tmem_dealloc(uint32_t base, uint32_t ncols) {
    asm volatile("tcgen05.dealloc.cta_group::1.sync.aligned.b32 %0, %1;"
                 :: "r"(base), "r"(ncols));
}
__device__ __forceinline__ void mma_f16_ss(uint32_t d_tmem, uint64_t a_desc,
                                           uint64_t b_desc, uint32_t idesc,
                                           uint32_t enable) {
    asm volatile(
        "{\n\t.reg .pred p;\n\t"
        "setp.ne.u32 p, %5, 0;\n\t"
        "tcgen05.mma.cta_group::1.kind::f16 [%0], %1, %2, %3, {%4, %4, %4, %4}, p;\n\t}"
        :: "r"(d_tmem), "l"(a_desc), "l"(b_desc), "r"(idesc), "r"(0u), "r"(enable)
        : "memory");
}
__device__ __forceinline__ void tc_commit(uint32_t mbar) {
    asm volatile(
        "tcgen05.commit.cta_group::1.mbarrier::arrive::one.shared::cluster.b64 [%0];"
        :: "r"(mbar) : "memory");
}
__device__ __forceinline__ void tc_fence_after() {
    asm volatile("tcgen05.fence::after_thread_sync;" ::: "memory");
}
__device__ __forceinline__ void tc_fence_before() {
    asm volatile("tcgen05.fence::before_thread_sync;" ::: "memory");
}
__device__ __forceinline__ void ldtm_x32(uint32_t* r, uint32_t addr) {
    asm volatile(
        "tcgen05.ld.sync.aligned.32x32b.x32.b32 "
        "{%0,%1,%2,%3,%4,%5,%6,%7,%8,%9,%10,%11,%12,%13,%14,%15,"
        "%16,%17,%18,%19,%20,%21,%22,%23,%24,%25,%26,%27,%28,%29,%30,%31}, [%32];"
        : "=r"(r[0]), "=r"(r[1]), "=r"(r[2]), "=r"(r[3]),
          "=r"(r[4]), "=r"(r[5]), "=r"(r[6]), "=r"(r[7]),
          "=r"(r[8]), "=r"(r[9]), "=r"(r[10]), "=r"(r[11]),
          "=r"(r[12]), "=r"(r[13]), "=r"(r[14]), "=r"(r[15]),
          "=r"(r[16]), "=r"(r[17]), "=r"(r[18]), "=r"(r[19]),
          "=r"(r[20]), "=r"(r[21]), "=r"(r[22]), "=r"(r[23]),
          "=r"(r[24]), "=r"(r[25]), "=r"(r[26]), "=r"(r[27]),
          "=r"(r[28]), "=r"(r[29]), "=r"(r[30]), "=r"(r[31])
        : "r"(addr));
}
__device__ __forceinline__ void tc_wait_ld() {
    asm volatile("tcgen05.wait::ld.sync.aligned;" ::: "memory");
}
// SW128 K-major SMEM descriptor (version=1, LBO=1, SBO=64)
__device__ __forceinline__ uint64_t make_desc(uint32_t smem_addr) {
    const uint64_t base =
        (uint64_t(2) << 61) | (uint64_t(1) << 46) | (uint64_t(64) << 32) | (uint64_t(1) << 16);
    return base | ((uint64_t)(smem_addr >> 4) & 0x3FFF);
}
// idesc cg1: dtype F32 (1<<4), fp16 a/b, N=256 (32<<17), M=128 (8<<24)
#define IDESC 0x8400010u
#endif  // TC_PATH

// ---------------------------------------------------------------------------
// k0: zero the flag array (runs before the fused kernel on every replay)
// ---------------------------------------------------------------------------
__global__ void zero_flags_kernel() {
    int i = blockIdx.x * blockDim.x + threadIdx.x;
    if (i < 6145) g_flags[i] = 0;
}

// ---------------------------------------------------------------------------
// warp-level block conversion (one 16KB SW128 block per call)
//   b (kc-major): kc = b / (WPC+XPC); r = b % ...; r<WPC -> W block, else X.
// ---------------------------------------------------------------------------
__device__ __forceinline__ void prep_block(int b, const float* __restrict__ x,
                                           const int* __restrict__ packed,
                                           float s, int K, int KC,
                                           int WPC, int PERKC) {
    const int lane = threadIdx.x & 31;
    const int kc = b / PERKC;
    const int r  = b - kc * PERKC;

    if (r < WPC) {
        const int n2 = r >> 1, half = r & 1;
        const int bW = (n2 * KC + kc) * 2 + half;
        const int K2 = K >> 1;
        const int nbase = n2 * 256 + half * 128;
        char* outb = reinterpret_cast<char*>(g_W) + (size_t)bW * BLK_BYTES;
#pragma unroll 4
        for (int it = 0; it < 32; ++it) {
            const int u = lane + it * 32;
            const int row = u >> 3, cg = u & 7;
            const int4 v = *reinterpret_cast<const int4*>(
                packed + (size_t)(nbase + row) * K2 + kc * 32 + cg * 4);
            __half o[8];
            const int b4[4] = {v.x, v.y, v.z, v.w};
#pragma unroll
            for (int j = 0; j < 4; ++j) {
                int hi = b4[j] >> 4;
                int lo = ((b4[j] & 15) ^ 8) - 8;
                o[2 * j]     = __float2half_rn((float)hi * s);
                o[2 * j + 1] = __float2half_rn((float)lo * s);
            }
            *reinterpret_cast<uint4*>(outb + swz128((uint32_t)(row * 128 + cg * 16))) =
                *reinterpret_cast<const uint4*>(o);
        }
        __syncwarp();
        if (lane == 0) {
            st_rel(&g_flags[bW], 1);
            __threadfence();
            atomicAdd(&g_flags[6144], 1);
        }
    } else {
        const int mb = r - WPC;
        const int bX = mb * KC + kc;
        const float* xin = x + (size_t)(mb * 128) * K + kc * 64;
        char* outb = reinterpret_cast<char*>(g_X) + (size_t)bX * BLK_BYTES;
#pragma unroll 4
        for (int it = 0; it < 32; ++it) {
            const int u = lane + it * 32;
            const int row = u >> 3, cg = u & 7;
            const float4* src = reinterpret_cast<const float4*>(
                xin + (size_t)row * K + cg * 8);
            const float4 a = src[0];
            const float4 c = src[1];
            __half o[8];
            o[0] = __float2half_rn(a.x); o[1] = __float2half_rn(a.y);
            o[2] = __float2half_rn(a.z); o[3] = __float2half_rn(a.w);
            o[4] = __float2half_rn(c.x); o[5] = __float2half_rn(c.y);
            o[6] = __float2half_rn(c.z); o[7] = __float2half_rn(c.w);
            *reinterpret_cast<uint4*>(outb + swz128((uint32_t)(row * 128 + cg * 16))) =
                *reinterpret_cast<const uint4*>(o);
        }
        __syncwarp();
        if (lane == 0) {
            st_rel(&g_flags[2048 + bX], 1);
            __threadfence();
            atomicAdd(&g_flags[6144], 1);
        }
    }
}

// ---------------------------------------------------------------------------
// k1: fused persistent GEMM (R10 structure) + overlapped prepass.
// ---------------------------------------------------------------------------
__global__ __launch_bounds__(THREADS, 1)
void gemm_kernel(const float* __restrict__ x,
                 const int* __restrict__ packed,
                 const float* __restrict__ scale_p,
                 const float* __restrict__ bias,
                 float* __restrict__ Out,
                 int M, int N, int K, int ntiles) {
    extern __shared__ char smem[];
    const uint32_t sbase = smem_u32(smem);
    const int tid  = threadIdx.x;
    const int wid  = tid >> 5;
    const int lane = tid & 31;

    const int KC      = K / KC_ELEMS;            // 64
    const int TILES_M = M / 128;                 // 64
    const int WPC     = N / 128;                 // 32 W blocks per kc
    const int XPC     = M / 128;                 // 64 X blocks per kc
    const int PERKC   = WPC + XPC;               // 96
    const int TOTALB  = KC * PERKC;              // 6144

#if TC_PATH
    const uint32_t full0  = sbase;
    const uint32_t empty0 = sbase + 32;
    const uint32_t done0  = sbase + 64;
    const uint32_t efree0 = sbase + 80;
    const uint32_t tslot  = sbase + 96;

    if (tid == 0) {
#pragma unroll
        for (int s = 0; s < STAGES; ++s) {
            mbar_init(full0 + s * 8, 1);
            mbar_init(empty0 + s * 8, 1);
        }
        mbar_init(done0, 1);     mbar_init(done0 + 8, 1);
        mbar_init(efree0, 8);    mbar_init(efree0 + 8, 8);
    }
    __syncthreads();

    if (wid == 8) {
        tmem_alloc(tslot, 512);
        tmem_relinquish();
    }
    __syncthreads();
    uint32_t tmem_base;
    asm volatile("ld.shared.b32 %0, [%1];" : "=r"(tmem_base) : "r"(tslot));

    // ==================== producer: warp 8, lane 0 ====================
    if (tid == 256) {
        int s = 0, ph = 1;
        bool allrdy = false;
        for (int t = blockIdx.x; t < ntiles; t += gridDim.x) {
            const int mb = t % TILES_M;
            const int nb = t / TILES_M;
            const char* Asrc = reinterpret_cast<const char*>(g_X) +
                               (size_t)mb * KC * BLK_BYTES;
            const char* Bsrc = reinterpret_cast<const char*>(g_W) +
                               (size_t)nb * KC * 2 * BLK_BYTES;
            for (int i = 0; i < KC; ++i) {
                mbar_wait(empty0 + s * 8, ph);
                if (!allrdy) {
                    if (ld_acq(&g_flags[6144]) == TOTALB) {
                        allrdy = true;
                    } else {
                        const int fX  = 2048 + mb * KC + i;
                        const int fW0 = (nb * KC + i) * 2;
                        while (ld_acq(&g_flags[fX]) == 0)      __nanosleep(64);
                        while (ld_acq(&g_flags[fW0]) == 0)     __nanosleep(64);
                        while (ld_acq(&g_flags[fW0 + 1]) == 0) __nanosleep(64);
                    }
                    fence_proxy_async_();        // order generic writes before TMA reads
                }
                const uint32_t fb = full0 + s * 8;
                mbar_expect_tx(fb, STAGE_BYTES);
                const uint32_t stg = sbase + SMEM_STAGE0 + s * STAGE_BYTES;
                bulk_g2s(stg,             Asrc + (size_t)i * BLK_BYTES,     BLK_BYTES,     fb);
                bulk_g2s(stg + BLK_BYTES, Bsrc + (size_t)i * 2 * BLK_BYTES, 2 * BLK_BYTES, fb);
                if (++s == STAGES) { s = 0; ph ^= 1; }
            }
        }
    }

    // ==================== MMA issuer: warp 9, lane 0 ====================
    if (tid == 288) {
        int s = 0, ph = 0;
        int j = 0;
        for (int t = blockIdx.x; t < ntiles; t += gridDim.x, ++j) {
            const int buf = j & 1;
            const int u   = j >> 1;
            if (u > 0) mbar_wait(efree0 + buf * 8, (u - 1) & 1);
            tc_fence_after();
            const uint32_t dacc = tmem_base + buf * 256;
            for (int i = 0; i < KC; ++i) {
                mbar_wait(full0 + s * 8, ph);
                const uint32_t stg = sbase + SMEM_STAGE0 + s * STAGE_BYTES;
                uint64_t ad = make_desc(stg);
                uint64_t bd = make_desc(stg + BLK_BYTES);
#pragma unroll
                for (int ks = 0; ks < 4; ++ks) {
                    mma_f16_ss(dacc, ad + ks * 2, bd + ks * 2, IDESC,
                               (i > 0 || ks > 0) ? 1u : 0u);
                }
                tc_commit(empty0 + s * 8);
                if (++s == STAGES) { s = 0; ph ^= 1; }
            }
            tc_commit(done0 + buf * 8);
        }
    }

    // ============ epilogue warps 0-7: prepass first, then epilogue ============
    if (wid < 8) {
        // ---- overlapped prepass (kc-major so early chunks unblock first) ----
        {
            const float s = __ldg(scale_p);
            const int gw = blockIdx.x * 8 + wid;
            const int nw = gridDim.x * 8;
            for (int b = gw; b < TOTALB; b += nw)
                prep_block(b, x, packed, s, K, KC, WPC, PERKC);
        }

        // ---- epilogue ----
        const int subp    = wid & 3;
        const int colhalf = wid >> 2;
        int j = 0;
        for (int t = blockIdx.x; t < ntiles; t += gridDim.x, ++j) {
            const int buf = j & 1;
            const int u   = j >> 1;
            mbar_wait(done0 + buf * 8, u & 1);
            tc_fence_after();

            const int mb = t % TILES_M;
            const int nb = t / TILES_M;
            const int row = mb * 128 + subp * 32 + lane;
            float* orow = Out + (size_t)row * N + nb * 256 + colhalf * 128;
            const float* brow = bias + nb * 256 + colhalf * 128;
            const uint32_t tacc = tmem_base + buf * 256 + colhalf * 128;

#pragma unroll
            for (int cb = 0; cb < 4; ++cb) {
                uint32_t r32[32];
                ldtm_x32(r32, tacc + cb * 32);
                tc_wait_ld();
                float o[32];
#pragma unroll
                for (int q = 0; q < 8; ++q) {
                    const float4 bf = *reinterpret_cast<const float4*>(brow + cb * 32 + q * 4);
                    const float bfv[4] = {bf.x, bf.y, bf.z, bf.w};
#pragma unroll
                    for (int e = 0; e < 4; ++e) {
                        const int c = q * 4 + e;
                        __half h  = __float2half_rn(__uint_as_float(r32[c]));
                        __half hb = __float2half_rn(bfv[e]);
                        o[c] = __half2float(__hadd(h, hb));
                    }
                }
#pragma unroll
                for (int q = 0; q < 8; ++q) {
                    reinterpret_cast<float4*>(orow + cb * 32)[q] =
                        make_float4(o[4 * q], o[4 * q + 1], o[4 * q + 2], o[4 * q + 3]);
                }
            }
            tc_fence_before();
            if (lane == 0) mbar_arrive(efree0 + buf * 8);
        }
    }

    __syncthreads();
    if (wid == 8) tmem_dealloc(tmem_base, 512);

#else
    // =============== compile-only fallback (never selected on GB300) =======
    const int K2 = K >> 1;
    for (int t = blockIdx.x; t < ntiles; t += gridDim.x) {
        const int mb = t % TILES_M;
        const int nb = t / TILES_M;
        for (int rr = tid; rr < 128; rr += THREADS) {
            const int m = mb * 128 + rr;
            for (int c = 0; c < 256; ++c) {
                const int n = nb * 256 + c;
                float acc = 0.0f;
                const float s = scale_p[0];
                for (int k = 0; k < K; ++k) {
                    int byte = packed[(size_t)n * K2 + (k >> 1)];
                    int q = (k & 1) ? (((byte & 15) ^ 8) - 8) : (byte >> 4);
                    float wv = __half2float(__float2half_rn((float)q * s));
                    float xv = __half2float(__float2half_rn(x[(size_t)m * K + k]));
                    acc += xv * wv;
                }
                __half h = __hadd(__float2half_rn(acc), __float2half_rn(bias[n]));
                Out[(size_t)m * N + n] = __half2float(h);
            }
        }
    }
#endif
}

// ---------------------------------------------------------------------------
extern "C" void kernel_launch(void* const* d_in, const int* in_sizes, int n_in,
                              void* d_out, int out_size) {
    const float* x     = (const float*)d_in[0];
    const int*   wq    = (const int*)d_in[1];
    const float* scale = (const float*)d_in[2];
    const float* bias  = (const float*)d_in[3];
    float*       out   = (float*)d_out;

    const int O = in_sizes[3];                    // 4096
    const int K = (in_sizes[1] / O) * 2;          // 4096
    const int M = in_sizes[0] / K;                // 8192
    const int N = O;
    const int ntiles = (M / 128) * (N / 256);     // 1024

    zero_flags_kernel<<<7, 1024>>>();

    int nsm = 148;
    cudaDeviceGetAttribute(&nsm, cudaDevAttrMultiProcessorCount, 0);

    cudaFuncSetAttribute(gemm_kernel,
                         cudaFuncAttributeMaxDynamicSharedMemorySize,
                         SMEM_TOTAL_GEMM);
    gemm_kernel<<<nsm, THREADS, SMEM_TOTAL_GEMM>>>(x, wq, scale, bias, out,
                                                   M, N, K, ntiles);
}